// round 1
// baseline (speedup 1.0000x reference)
#include <cuda_runtime.h>

#define N_NODES 100000
#define N_EDGES 1600000
#define D 128
#define H 8
#define DH 16
#define DFF 256

// ---------------- scratch (device globals; no allocation allowed) ----------
__device__ float g_Q[N_NODES * D];
__device__ float g_K[N_NODES * D];
__device__ float g_V[N_NODES * D];
__device__ float g_wV[N_NODES * D];
__device__ float g_z[N_NODES * H];

// ---------------- zero wV / z each call ------------------------------------
__global__ void zero_kernel() {
    long i = (long)blockIdx.x * blockDim.x + threadIdx.x;
    long stride = (long)gridDim.x * blockDim.x;
    float4 zz = make_float4(0.f, 0.f, 0.f, 0.f);
    long n4 = (long)N_NODES * D / 4;
    for (long j = i; j < n4; j += stride) ((float4*)g_wV)[j] = zz;
    long nz = (long)N_NODES * H / 4;
    for (long j = i; j < nz; j += stride) ((float4*)g_z)[j] = zz;
}

// ---------------- QKV projection: h[N,128] @ {Wq,Wk,Wv} --------------------
// Block: 256 threads, 64-node tile. Thread computes 8 nodes x 4 cols per weight.
__global__ __launch_bounds__(256) void qkv_kernel(
    const float* __restrict__ h,
    const float* __restrict__ Wq, const float* __restrict__ Wk,
    const float* __restrict__ Wv)
{
    __shared__ float hs[64 * D];
    int t = threadIdx.x;
    int n0 = blockIdx.x * 64;

    // load h tile (zero-pad tail)
    for (int i = t; i < 64 * (D / 4); i += 256) {
        int n = i / (D / 4);
        float4 v = make_float4(0.f, 0.f, 0.f, 0.f);
        if (n0 + n < N_NODES)
            v = ((const float4*)h)[(long)(n0 + n) * (D / 4) + (i % (D / 4))];
        ((float4*)hs)[i] = v;
    }
    __syncthreads();

    int col = (t & 31) * 4;
    int nb  = (t >> 5) * 8;

    const float* Ws[3] = {Wq, Wk, Wv};
    float* Os[3] = {g_Q, g_K, g_V};

#pragma unroll
    for (int w = 0; w < 3; w++) {
        const float* __restrict__ W = Ws[w];
        float4 acc[8];
#pragma unroll
        for (int i = 0; i < 8; i++) acc[i] = make_float4(0.f, 0.f, 0.f, 0.f);
#pragma unroll 4
        for (int k = 0; k < D; k++) {
            float4 wv = *(const float4*)&W[k * D + col];
#pragma unroll
            for (int i = 0; i < 8; i++) {
                float hv = hs[(nb + i) * D + k];
                acc[i].x += hv * wv.x; acc[i].y += hv * wv.y;
                acc[i].z += hv * wv.z; acc[i].w += hv * wv.w;
            }
        }
        float* O = Os[w];
#pragma unroll
        for (int i = 0; i < 8; i++) {
            int n = n0 + nb + i;
            if (n < N_NODES) *(float4*)&O[(long)n * D + col] = acc[i];
        }
    }
}

// ---------------- edge kernel: score + scatter (fused) ---------------------
// One warp per edge. Lane l covers feature elems [4l,4l+4) -> head = l/4.
__global__ __launch_bounds__(256) void edge_kernel(
    const int* __restrict__ src, const int* __restrict__ dst)
{
    int e = blockIdx.x * 8 + (threadIdx.x >> 5);
    if (e >= N_EDGES) return;
    int lane = threadIdx.x & 31;
    int s = src[e];
    int d = dst[e];

    float4 kv = *(const float4*)&g_K[(long)s * D + lane * 4];
    float4 qv = *(const float4*)&g_Q[(long)d * D + lane * 4];
    float ps = kv.x * qv.x + kv.y * qv.y + kv.z * qv.z + kv.w * qv.w;
    // reduce within 4-lane head group (butterfly -> all 4 lanes get the sum)
    ps += __shfl_xor_sync(0xffffffff, ps, 1);
    ps += __shfl_xor_sync(0xffffffff, ps, 2);
    float sc = __expf(fminf(fmaxf(ps * 0.25f, -5.f), 5.f));   // 1/sqrt(16)=0.25

    float4 vv = *(const float4*)&g_V[(long)s * D + lane * 4];
    float* wp = &g_wV[(long)d * D + lane * 4];
    asm volatile("red.global.add.v4.f32 [%0], {%1,%2,%3,%4};"
                 :: "l"(wp), "f"(vv.x * sc), "f"(vv.y * sc),
                    "f"(vv.z * sc), "f"(vv.w * sc)
                 : "memory");
    if ((lane & 3) == 0) {
        asm volatile("red.global.add.f32 [%0], %1;"
                     :: "l"(&g_z[(long)d * H + (lane >> 2)]), "f"(sc)
                     : "memory");
    }
}

// ---------------- epilogue: attn-norm + Wo + LN1 + FFN + LN2 ---------------
// Block: 256 threads, 32-node tile (100000 = 32*3125 exactly, no tail).
// Shared (48KB): XS[32][128] at 0; A[32][128] at 4096 (reused as FS[32][256]).
__device__ __forceinline__ void warp_ln4(float* buf, const float* __restrict__ g,
                                         const float* __restrict__ b,
                                         float* outbase, int t)
{
    int w = t >> 5, lane = t & 31;
    float4 gv = *(const float4*)&g[lane * 4];
    float4 bv = *(const float4*)&b[lane * 4];
#pragma unroll
    for (int i = 0; i < 4; i++) {
        int n = w * 4 + i;
        float4 v = *(float4*)&buf[n * D + lane * 4];
        float s  = v.x + v.y + v.z + v.w;
        float sq = v.x * v.x + v.y * v.y + v.z * v.z + v.w * v.w;
#pragma unroll
        for (int off = 16; off >= 1; off >>= 1) {
            s  += __shfl_xor_sync(0xffffffff, s, off);
            sq += __shfl_xor_sync(0xffffffff, sq, off);
        }
        float mu  = s * (1.f / D);
        float var = sq * (1.f / D) - mu * mu;
        float rs  = rsqrtf(var + 1e-5f);
        float4 o;
        o.x = (v.x - mu) * rs * gv.x + bv.x;
        o.y = (v.y - mu) * rs * gv.y + bv.y;
        o.z = (v.z - mu) * rs * gv.z + bv.z;
        o.w = (v.w - mu) * rs * gv.w + bv.w;
        *(float4*)&outbase[n * D + lane * 4] = o;
    }
}

__global__ __launch_bounds__(256) void epi_kernel(
    const float* __restrict__ h,
    const float* __restrict__ Wo, const float* __restrict__ bo,
    const float* __restrict__ ln1g, const float* __restrict__ ln1b,
    const float* __restrict__ W1, const float* __restrict__ b1,
    const float* __restrict__ W2, const float* __restrict__ b2,
    const float* __restrict__ ln2g, const float* __restrict__ ln2b,
    float* __restrict__ out)
{
    __shared__ float sm[12288];           // 48KB
    float* XS = sm;                       // [32][128]
    float* A  = sm + 4096;                // [32][128] h_attn; later reused as FS
    float* FS = sm + 4096;                // [32][256] (A is dead by then)

    int t = threadIdx.x;
    int n0 = blockIdx.x * 32;

    // step 1: h_attn = wV / (z + eps). Thread covers one head of one node.
    {
        int nl = t >> 3;                  // 0..31 local node
        int head = t & 7;
        int gn = n0 + nl;
        float inv = 1.f / (g_z[(long)gn * H + head] + 1e-6f);
        const float4* s4 = (const float4*)&g_wV[(long)gn * D + head * 16];
        float4* a4 = (float4*)&A[nl * D + head * 16];
#pragma unroll
        for (int j = 0; j < 4; j++) {
            float4 v = s4[j];
            v.x *= inv; v.y *= inv; v.z *= inv; v.w *= inv;
            a4[j] = v;
        }
    }
    __syncthreads();

    int col = (t & 31) * 4;
    int nb4 = (t >> 5) * 4;

    // step 2: XS = h + A @ Wo + bo
    {
        float4 acc[4];
#pragma unroll
        for (int i = 0; i < 4; i++) acc[i] = make_float4(0.f, 0.f, 0.f, 0.f);
#pragma unroll 4
        for (int k = 0; k < D; k++) {
            float4 wv = *(const float4*)&Wo[k * D + col];
#pragma unroll
            for (int i = 0; i < 4; i++) {
                float a = A[(nb4 + i) * D + k];
                acc[i].x += a * wv.x; acc[i].y += a * wv.y;
                acc[i].z += a * wv.z; acc[i].w += a * wv.w;
            }
        }
        float4 bov = *(const float4*)&bo[col];
#pragma unroll
        for (int i = 0; i < 4; i++) {
            float4 hv = *(const float4*)&h[(long)(n0 + nb4 + i) * D + col];
            float4 x;
            x.x = hv.x + acc[i].x + bov.x;
            x.y = hv.y + acc[i].y + bov.y;
            x.z = hv.z + acc[i].z + bov.z;
            x.w = hv.w + acc[i].w + bov.w;
            *(float4*)&XS[(nb4 + i) * D + col] = x;
        }
    }
    __syncthreads();

    // step 3: LN1 in place on XS
    warp_ln4(XS, ln1g, ln1b, XS, t);
    __syncthreads();

    // step 4: FS = relu(XS @ W1 + b1)   (A is dead; FS overlaps it)
    {
        int c1  = (t & 63) * 4;           // 0..252 over DFF=256
        int nb8 = (t >> 6) * 8;           // 8 nodes
        float4 acc[8];
#pragma unroll
        for (int i = 0; i < 8; i++) acc[i] = make_float4(0.f, 0.f, 0.f, 0.f);
#pragma unroll 4
        for (int k = 0; k < D; k++) {
            float4 wv = *(const float4*)&W1[k * DFF + c1];
#pragma unroll
            for (int i = 0; i < 8; i++) {
                float a = XS[(nb8 + i) * D + k];
                acc[i].x += a * wv.x; acc[i].y += a * wv.y;
                acc[i].z += a * wv.z; acc[i].w += a * wv.w;
            }
        }
        float4 b1v = *(const float4*)&b1[c1];
#pragma unroll
        for (int i = 0; i < 8; i++) {
            float4 f;
            f.x = fmaxf(acc[i].x + b1v.x, 0.f);
            f.y = fmaxf(acc[i].y + b1v.y, 0.f);
            f.z = fmaxf(acc[i].z + b1v.z, 0.f);
            f.w = fmaxf(acc[i].w + b1v.w, 0.f);
            *(float4*)&FS[(nb8 + i) * DFF + c1] = f;
        }
    }
    __syncthreads();

    // step 5: pre-LN2 = XS + FS @ W2 + b2  (accumulate into registers, then
    // write into XS; safe because each thread writes exactly the cols it owns)
    {
        float4 acc[4];
#pragma unroll
        for (int i = 0; i < 4; i++) acc[i] = make_float4(0.f, 0.f, 0.f, 0.f);
#pragma unroll 4
        for (int k = 0; k < DFF; k++) {
            float4 wv = *(const float4*)&W2[k * D + col];
#pragma unroll
            for (int i = 0; i < 4; i++) {
                float f = FS[(nb4 + i) * DFF + k];
                acc[i].x += f * wv.x; acc[i].y += f * wv.y;
                acc[i].z += f * wv.z; acc[i].w += f * wv.w;
            }
        }
        __syncthreads();   // all FS reads done before overwriting XS
        float4 b2v = *(const float4*)&b2[col];
#pragma unroll
        for (int i = 0; i < 4; i++) {
            float4 x = *(float4*)&XS[(nb4 + i) * D + col];
            x.x += acc[i].x + b2v.x;
            x.y += acc[i].y + b2v.y;
            x.z += acc[i].z + b2v.z;
            x.w += acc[i].w + b2v.w;
            *(float4*)&XS[(nb4 + i) * D + col] = x;
        }
    }
    __syncthreads();

    // step 6: LN2 -> global out
    warp_ln4(XS, ln2g, ln2b, out + (long)n0 * D, t);
}

// ---------------- launch ----------------------------------------------------
extern "C" void kernel_launch(void* const* d_in, const int* in_sizes, int n_in,
                              void* d_out, int out_size)
{
    const float* h    = (const float*)d_in[0];
    const int*   src  = (const int*)  d_in[1];
    const int*   dst  = (const int*)  d_in[2];
    const float* Wq   = (const float*)d_in[3];
    const float* Wk   = (const float*)d_in[4];
    const float* Wv   = (const float*)d_in[5];
    const float* Wo   = (const float*)d_in[6];
    const float* bo   = (const float*)d_in[7];
    const float* ln1g = (const float*)d_in[8];
    const float* ln1b = (const float*)d_in[9];
    const float* W1   = (const float*)d_in[10];
    const float* b1   = (const float*)d_in[11];
    const float* W2   = (const float*)d_in[12];
    const float* b2   = (const float*)d_in[13];
    const float* ln2g = (const float*)d_in[14];
    const float* ln2b = (const float*)d_in[15];
    float* out = (float*)d_out;

    zero_kernel<<<2048, 256>>>();
    qkv_kernel<<<(N_NODES + 63) / 64, 256>>>(h, Wq, Wk, Wv);
    edge_kernel<<<(N_EDGES + 7) / 8, 256>>>(src, dst);
    epi_kernel<<<N_NODES / 32, 256>>>(h, Wo, bo, ln1g, ln1b,
                                      W1, b1, W2, b2, ln2g, ln2b, out);
}

// round 2
// speedup vs baseline: 1.1210x; 1.1210x over previous
#include <cuda_runtime.h>

#define N_NODES 100000
#define N_EDGES 1600000
#define D 128
#define H 8
#define DH 16
#define DFF 256

// ---------------- scratch (device globals; no allocation allowed) ----------
__device__ float g_Q[N_NODES * D];
__device__ float g_K[N_NODES * D];
__device__ float g_V[N_NODES * D];
__device__ float g_wV[N_NODES * D];
__device__ float g_z[N_NODES * H];

// ---------------- packed f32x2 helpers -------------------------------------
typedef unsigned long long u64;

__device__ __forceinline__ u64 ffma2(u64 a, u64 b, u64 c) {
    u64 d;
    asm("fma.rn.f32x2 %0, %1, %2, %3;" : "=l"(d) : "l"(a), "l"(b), "l"(c));
    return d;
}
__device__ __forceinline__ u64 dup2(float s) {
    u64 d;
    asm("mov.b64 %0, {%1, %1};" : "=l"(d) : "f"(s));
    return d;
}
union V4 { u64 p[2]; float4 f; };

// ---------------- QKV projection: h[N,128] @ {Wq,Wk,Wv} --------------------
// Block: 256 threads, 64-node tile. Thread computes 8 nodes x 4 cols (2 packed
// col-pairs) per weight using fma.rn.f32x2. Also zeroes this tile's wV/z.
__global__ __launch_bounds__(256) void qkv_kernel(
    const float* __restrict__ h,
    const float* __restrict__ Wq, const float* __restrict__ Wk,
    const float* __restrict__ Wv)
{
    __shared__ float hs[64 * D];
    int t = threadIdx.x;
    int n0 = blockIdx.x * 64;

    // zero wV rows for this tile (64 nodes x 32 float4)
    float4 zz = make_float4(0.f, 0.f, 0.f, 0.f);
    for (int i = t; i < 64 * (D / 4); i += 256) {
        int n = n0 + i / (D / 4);
        if (n < N_NODES)
            ((float4*)g_wV)[(long)n * (D / 4) + (i % (D / 4))] = zz;
    }
    // zero z rows for this tile (64 nodes x 8 floats = 128 float4)
    for (int i = t; i < 64 * H / 4; i += 256) {
        long idx = (long)n0 * (H / 4) + i;
        if (idx < (long)N_NODES * H / 4) ((float4*)g_z)[idx] = zz;
    }

    // load h tile (zero-pad tail)
    for (int i = t; i < 64 * (D / 4); i += 256) {
        int n = i / (D / 4);
        float4 v = zz;
        if (n0 + n < N_NODES)
            v = ((const float4*)h)[(long)(n0 + n) * (D / 4) + (i % (D / 4))];
        ((float4*)hs)[i] = v;
    }
    __syncthreads();

    int col = (t & 31) * 4;
    int nb  = (t >> 5) * 8;

    const float* Ws[3] = {Wq, Wk, Wv};
    float* Os[3] = {g_Q, g_K, g_V};

#pragma unroll
    for (int w = 0; w < 3; w++) {
        const float* __restrict__ W = Ws[w];
        u64 acc[8][2];
#pragma unroll
        for (int i = 0; i < 8; i++) { acc[i][0] = 0ull; acc[i][1] = 0ull; }
#pragma unroll 4
        for (int k = 0; k < D; k += 2) {
            ulonglong2 w0 = *(const ulonglong2*)&W[k * D + col];
            ulonglong2 w1 = *(const ulonglong2*)&W[(k + 1) * D + col];
#pragma unroll
            for (int i = 0; i < 8; i++) {
                float2 hk = *(const float2*)&hs[(nb + i) * D + k];
                u64 d0 = dup2(hk.x), d1 = dup2(hk.y);
                acc[i][0] = ffma2(d0, w0.x, acc[i][0]);
                acc[i][1] = ffma2(d0, w0.y, acc[i][1]);
                acc[i][0] = ffma2(d1, w1.x, acc[i][0]);
                acc[i][1] = ffma2(d1, w1.y, acc[i][1]);
            }
        }
        float* O = Os[w];
#pragma unroll
        for (int i = 0; i < 8; i++) {
            int n = n0 + nb + i;
            if (n < N_NODES) {
                V4 v; v.p[0] = acc[i][0]; v.p[1] = acc[i][1];
                *(float4*)&O[(long)n * D + col] = v.f;
            }
        }
    }
}

// ---------------- edge kernel: score + scatter (fused) ---------------------
// One warp per edge. Lane l covers feature elems [4l,4l+4) -> head = l/4.
__global__ __launch_bounds__(256) void edge_kernel(
    const int* __restrict__ src, const int* __restrict__ dst)
{
    int e = blockIdx.x * 8 + (threadIdx.x >> 5);
    if (e >= N_EDGES) return;
    int lane = threadIdx.x & 31;
    int s = src[e];
    int d = dst[e];

    float4 kv = *(const float4*)&g_K[(long)s * D + lane * 4];
    float4 qv = *(const float4*)&g_Q[(long)d * D + lane * 4];
    float ps = kv.x * qv.x + kv.y * qv.y + kv.z * qv.z + kv.w * qv.w;
    ps += __shfl_xor_sync(0xffffffff, ps, 1);
    ps += __shfl_xor_sync(0xffffffff, ps, 2);
    float sc = __expf(fminf(fmaxf(ps * 0.25f, -5.f), 5.f));   // 1/sqrt(16)=0.25

    float4 vv = *(const float4*)&g_V[(long)s * D + lane * 4];
    float* wp = &g_wV[(long)d * D + lane * 4];
    asm volatile("red.global.add.v4.f32 [%0], {%1,%2,%3,%4};"
                 :: "l"(wp), "f"(vv.x * sc), "f"(vv.y * sc),
                    "f"(vv.z * sc), "f"(vv.w * sc)
                 : "memory");
    if ((lane & 3) == 0) {
        asm volatile("red.global.add.f32 [%0], %1;"
                     :: "l"(&g_z[(long)d * H + (lane >> 2)]), "f"(sc)
                     : "memory");
    }
}

// ---------------- epilogue: attn-norm + Wo + LN1 + FFN + LN2 ---------------
// Block: 256 threads, 32-node tile (100000 = 32*3125 exactly, no tail).
__device__ __forceinline__ void warp_ln4(float* buf, const float* __restrict__ g,
                                         const float* __restrict__ b,
                                         float* outbase, int t)
{
    int w = t >> 5, lane = t & 31;
    float4 gv = *(const float4*)&g[lane * 4];
    float4 bv = *(const float4*)&b[lane * 4];
#pragma unroll
    for (int i = 0; i < 4; i++) {
        int n = w * 4 + i;
        float4 v = *(float4*)&buf[n * D + lane * 4];
        float s  = v.x + v.y + v.z + v.w;
        float sq = v.x * v.x + v.y * v.y + v.z * v.z + v.w * v.w;
#pragma unroll
        for (int off = 16; off >= 1; off >>= 1) {
            s  += __shfl_xor_sync(0xffffffff, s, off);
            sq += __shfl_xor_sync(0xffffffff, sq, off);
        }
        float mu  = s * (1.f / D);
        float var = sq * (1.f / D) - mu * mu;
        float rs  = rsqrtf(var + 1e-5f);
        float4 o;
        o.x = (v.x - mu) * rs * gv.x + bv.x;
        o.y = (v.y - mu) * rs * gv.y + bv.y;
        o.z = (v.z - mu) * rs * gv.z + bv.z;
        o.w = (v.w - mu) * rs * gv.w + bv.w;
        *(float4*)&outbase[n * D + lane * 4] = o;
    }
}

__global__ __launch_bounds__(256) void epi_kernel(
    const float* __restrict__ h,
    const float* __restrict__ Wo, const float* __restrict__ bo,
    const float* __restrict__ ln1g, const float* __restrict__ ln1b,
    const float* __restrict__ W1, const float* __restrict__ b1,
    const float* __restrict__ W2, const float* __restrict__ b2,
    const float* __restrict__ ln2g, const float* __restrict__ ln2b,
    float* __restrict__ out)
{
    __shared__ float sm[12288];           // 48KB
    float* XS = sm;                       // [32][128]
    float* A  = sm + 4096;                // [32][128] h_attn; later reused as FS
    float* FS = sm + 4096;                // [32][256] (A is dead by then)

    int t = threadIdx.x;
    int n0 = blockIdx.x * 32;

    // step 1: h_attn = wV / (z + eps). Thread covers one head of one node.
    {
        int nl = t >> 3;
        int head = t & 7;
        int gn = n0 + nl;
        float inv = 1.f / (g_z[(long)gn * H + head] + 1e-6f);
        const float4* s4 = (const float4*)&g_wV[(long)gn * D + head * 16];
        float4* a4 = (float4*)&A[nl * D + head * 16];
#pragma unroll
        for (int j = 0; j < 4; j++) {
            float4 v = s4[j];
            v.x *= inv; v.y *= inv; v.z *= inv; v.w *= inv;
            a4[j] = v;
        }
    }
    __syncthreads();

    int col = (t & 31) * 4;
    int nb4 = (t >> 5) * 4;

    // step 2: XS = h + A @ Wo + bo
    {
        u64 acc[4][2];
#pragma unroll
        for (int i = 0; i < 4; i++) { acc[i][0] = 0ull; acc[i][1] = 0ull; }
#pragma unroll 4
        for (int k = 0; k < D; k += 2) {
            ulonglong2 w0 = *(const ulonglong2*)&Wo[k * D + col];
            ulonglong2 w1 = *(const ulonglong2*)&Wo[(k + 1) * D + col];
#pragma unroll
            for (int i = 0; i < 4; i++) {
                float2 ak = *(const float2*)&A[(nb4 + i) * D + k];
                u64 d0 = dup2(ak.x), d1 = dup2(ak.y);
                acc[i][0] = ffma2(d0, w0.x, acc[i][0]);
                acc[i][1] = ffma2(d0, w0.y, acc[i][1]);
                acc[i][0] = ffma2(d1, w1.x, acc[i][0]);
                acc[i][1] = ffma2(d1, w1.y, acc[i][1]);
            }
        }
        float4 bov = *(const float4*)&bo[col];
        __syncthreads();   // all A reads done (XS doesn't alias A, but keep order tight)
#pragma unroll
        for (int i = 0; i < 4; i++) {
            float4 hv = *(const float4*)&h[(long)(n0 + nb4 + i) * D + col];
            V4 v; v.p[0] = acc[i][0]; v.p[1] = acc[i][1];
            float4 x;
            x.x = hv.x + v.f.x + bov.x;
            x.y = hv.y + v.f.y + bov.y;
            x.z = hv.z + v.f.z + bov.z;
            x.w = hv.w + v.f.w + bov.w;
            *(float4*)&XS[(nb4 + i) * D + col] = x;
        }
    }
    __syncthreads();

    // step 3: LN1 in place on XS
    warp_ln4(XS, ln1g, ln1b, XS, t);
    __syncthreads();

    // step 4: FS = relu(XS @ W1 + b1)   (A is dead; FS overlaps it)
    {
        int c1  = (t & 63) * 4;
        int nb8 = (t >> 6) * 8;
        u64 acc[8][2];
#pragma unroll
        for (int i = 0; i < 8; i++) { acc[i][0] = 0ull; acc[i][1] = 0ull; }
#pragma unroll 2
        for (int k = 0; k < D; k += 2) {
            ulonglong2 w0 = *(const ulonglong2*)&W1[k * DFF + c1];
            ulonglong2 w1 = *(const ulonglong2*)&W1[(k + 1) * DFF + c1];
#pragma unroll
            for (int i = 0; i < 8; i++) {
                float2 xk = *(const float2*)&XS[(nb8 + i) * D + k];
                u64 d0 = dup2(xk.x), d1 = dup2(xk.y);
                acc[i][0] = ffma2(d0, w0.x, acc[i][0]);
                acc[i][1] = ffma2(d0, w0.y, acc[i][1]);
                acc[i][0] = ffma2(d1, w1.x, acc[i][0]);
                acc[i][1] = ffma2(d1, w1.y, acc[i][1]);
            }
        }
        float4 b1v = *(const float4*)&b1[c1];
        __syncthreads();   // XS reads done before FS (overlapping A region) writes? FS!=XS, but A==FS dead. Keep for safety.
#pragma unroll
        for (int i = 0; i < 8; i++) {
            V4 v; v.p[0] = acc[i][0]; v.p[1] = acc[i][1];
            float4 f;
            f.x = fmaxf(v.f.x + b1v.x, 0.f);
            f.y = fmaxf(v.f.y + b1v.y, 0.f);
            f.z = fmaxf(v.f.z + b1v.z, 0.f);
            f.w = fmaxf(v.f.w + b1v.w, 0.f);
            *(float4*)&FS[(nb8 + i) * DFF + c1] = f;
        }
    }
    __syncthreads();

    // step 5: pre-LN2 = XS + FS @ W2 + b2
    {
        u64 acc[4][2];
#pragma unroll
        for (int i = 0; i < 4; i++) { acc[i][0] = 0ull; acc[i][1] = 0ull; }
#pragma unroll 2
        for (int k = 0; k < DFF; k += 2) {
            ulonglong2 w0 = *(const ulonglong2*)&W2[k * D + col];
            ulonglong2 w1 = *(const ulonglong2*)&W2[(k + 1) * D + col];
#pragma unroll
            for (int i = 0; i < 4; i++) {
                float2 fk = *(const float2*)&FS[(nb4 + i) * DFF + k];
                u64 d0 = dup2(fk.x), d1 = dup2(fk.y);
                acc[i][0] = ffma2(d0, w0.x, acc[i][0]);
                acc[i][1] = ffma2(d0, w0.y, acc[i][1]);
                acc[i][0] = ffma2(d1, w1.x, acc[i][0]);
                acc[i][1] = ffma2(d1, w1.y, acc[i][1]);
            }
        }
        __syncthreads();   // all FS reads done before overwriting XS
        float4 b2v = *(const float4*)&b2[col];
#pragma unroll
        for (int i = 0; i < 4; i++) {
            float4 x = *(float4*)&XS[(nb4 + i) * D + col];
            V4 v; v.p[0] = acc[i][0]; v.p[1] = acc[i][1];
            x.x += v.f.x + b2v.x;
            x.y += v.f.y + b2v.y;
            x.z += v.f.z + b2v.z;
            x.w += v.f.w + b2v.w;
            *(float4*)&XS[(nb4 + i) * D + col] = x;
        }
    }
    __syncthreads();

    // step 6: LN2 -> global out
    warp_ln4(XS, ln2g, ln2b, out + (long)n0 * D, t);
}

// ---------------- launch ----------------------------------------------------
extern "C" void kernel_launch(void* const* d_in, const int* in_sizes, int n_in,
                              void* d_out, int out_size)
{
    const float* h    = (const float*)d_in[0];
    const int*   src  = (const int*)  d_in[1];
    const int*   dst  = (const int*)  d_in[2];
    const float* Wq   = (const float*)d_in[3];
    const float* Wk   = (const float*)d_in[4];
    const float* Wv   = (const float*)d_in[5];
    const float* Wo   = (const float*)d_in[6];
    const float* bo   = (const float*)d_in[7];
    const float* ln1g = (const float*)d_in[8];
    const float* ln1b = (const float*)d_in[9];
    const float* W1   = (const float*)d_in[10];
    const float* b1   = (const float*)d_in[11];
    const float* W2   = (const float*)d_in[12];
    const float* b2   = (const float*)d_in[13];
    const float* ln2g = (const float*)d_in[14];
    const float* ln2b = (const float*)d_in[15];
    float* out = (float*)d_out;

    qkv_kernel<<<(N_NODES + 63) / 64, 256>>>(h, Wq, Wk, Wv);
    edge_kernel<<<(N_EDGES + 7) / 8, 256>>>(src, dst);
    epi_kernel<<<N_NODES / 32, 256>>>(h, Wo, bo, ln1g, ln1b,
                                      W1, b1, W2, b2, ln2g, ln2b, out);
}

// round 3
// speedup vs baseline: 1.4562x; 1.2990x over previous
#include <cuda_runtime.h>

#define N_NODES 100000
#define N_EDGES 1600000
#define D 128
#define H 8
#define DH 16
#define DFF 256
#define CAP 96          // max in-degree capacity (Poisson mean 16; P(>96) ~ 0)

// ---------------- scratch (device globals; no allocation allowed) ----------
__device__ float g_Q[N_NODES * D];
__device__ float g_KV[(long)N_NODES * 2 * D];   // [node][K 0..127 | V 128..255]
__device__ float g_wV[N_NODES * D];
__device__ float g_z[N_NODES * H];
__device__ int   g_cnt[N_NODES];
__device__ int   g_csr[(long)N_NODES * CAP];    // src node ids, bucketed by dst

// ---------------- packed f32x2 helpers -------------------------------------
typedef unsigned long long u64;

__device__ __forceinline__ u64 ffma2(u64 a, u64 b, u64 c) {
    u64 d;
    asm("fma.rn.f32x2 %0, %1, %2, %3;" : "=l"(d) : "l"(a), "l"(b), "l"(c));
    return d;
}
__device__ __forceinline__ u64 dup2(float s) {
    u64 d;
    asm("mov.b64 %0, {%1, %1};" : "=l"(d) : "f"(s));
    return d;
}
union V4 { u64 p[2]; float4 f; };

// ---------------- zero in-degree counters ----------------------------------
__global__ void zero_cnt_kernel() {
    int i = blockIdx.x * blockDim.x + threadIdx.x;
    if (i < N_NODES) g_cnt[i] = 0;
}

// ---------------- bucket edges by dst --------------------------------------
__global__ __launch_bounds__(256) void scatter_kernel(
    const int* __restrict__ src, const int* __restrict__ dst)
{
    int e = blockIdx.x * 256 + threadIdx.x;
    if (e >= N_EDGES) return;
    int d = dst[e];
    int pos = atomicAdd(&g_cnt[d], 1);
    if (pos < CAP) g_csr[(long)d * CAP + pos] = src[e];
}

// ---------------- QKV projection: h[N,128] @ {Wq,Wk,Wv} --------------------
// grid = (tiles, 3): blockIdx.y selects the weight matrix. 256 threads,
// 64-node tile, thread computes 8 nodes x 4 cols via fma.rn.f32x2.
__global__ __launch_bounds__(256, 3) void qkv_kernel(
    const float* __restrict__ h,
    const float* __restrict__ Wq, const float* __restrict__ Wk,
    const float* __restrict__ Wv)
{
    __shared__ float hs[64 * D];
    int t = threadIdx.x;
    int n0 = blockIdx.x * 64;
    int wsel = blockIdx.y;

    // load h tile (zero-pad tail)
    float4 zz = make_float4(0.f, 0.f, 0.f, 0.f);
    for (int i = t; i < 64 * (D / 4); i += 256) {
        int n = i / (D / 4);
        float4 v = zz;
        if (n0 + n < N_NODES)
            v = ((const float4*)h)[(long)(n0 + n) * (D / 4) + (i % (D / 4))];
        ((float4*)hs)[i] = v;
    }
    __syncthreads();

    const float* __restrict__ W = (wsel == 0) ? Wq : (wsel == 1) ? Wk : Wv;

    int col = (t & 31) * 4;
    int nb  = (t >> 5) * 8;

    u64 acc[8][2];
#pragma unroll
    for (int i = 0; i < 8; i++) { acc[i][0] = 0ull; acc[i][1] = 0ull; }
#pragma unroll 4
    for (int k = 0; k < D; k += 2) {
        ulonglong2 w0 = *(const ulonglong2*)&W[k * D + col];
        ulonglong2 w1 = *(const ulonglong2*)&W[(k + 1) * D + col];
#pragma unroll
        for (int i = 0; i < 8; i++) {
            float2 hk = *(const float2*)&hs[(nb + i) * D + k];
            u64 d0 = dup2(hk.x), d1 = dup2(hk.y);
            acc[i][0] = ffma2(d0, w0.x, acc[i][0]);
            acc[i][1] = ffma2(d0, w0.y, acc[i][1]);
            acc[i][0] = ffma2(d1, w1.x, acc[i][0]);
            acc[i][1] = ffma2(d1, w1.y, acc[i][1]);
        }
    }

#pragma unroll
    for (int i = 0; i < 8; i++) {
        int n = n0 + nb + i;
        if (n < N_NODES) {
            V4 v; v.p[0] = acc[i][0]; v.p[1] = acc[i][1];
            float* O = (wsel == 0) ? &g_Q[(long)n * D]
                     : (wsel == 1) ? &g_KV[(long)n * 2 * D]
                                   : &g_KV[(long)n * 2 * D + D];
            *(float4*)&O[col] = v.f;
        }
    }
}

// ---------------- aggregation: one warp per dst node -----------------------
// Lane l covers feature elems [4l,4l+4) -> head = l/4. No atomics: each warp
// owns its dst row. K/V gathered with 1-deep software pipeline.
__global__ __launch_bounds__(256) void agg_kernel()
{
    int n = blockIdx.x * 8 + (threadIdx.x >> 5);   // 12500 blocks exact
    int lane = threadIdx.x & 31;

    float4 q = *(const float4*)&g_Q[(long)n * D + lane * 4];
    float4 acc = make_float4(0.f, 0.f, 0.f, 0.f);
    float accz = 0.f;

    int deg = g_cnt[n];
    if (deg > CAP) deg = CAP;
    const int* __restrict__ lst = &g_csr[(long)n * CAP];

    if (deg > 0) {
        int s = lst[0];
        const float* kvp = &g_KV[(long)s * 2 * D];
        float4 k = *(const float4*)&kvp[lane * 4];
        float4 v = *(const float4*)&kvp[D + lane * 4];
        for (int j = 0; j < deg; j++) {
            float4 kc = k, vc = v;
            if (j + 1 < deg) {
                int s2 = lst[j + 1];
                const float* kvp2 = &g_KV[(long)s2 * 2 * D];
                k = *(const float4*)&kvp2[lane * 4];
                v = *(const float4*)&kvp2[D + lane * 4];
            }
            float ps = kc.x * q.x + kc.y * q.y + kc.z * q.z + kc.w * q.w;
            ps += __shfl_xor_sync(0xffffffff, ps, 1);
            ps += __shfl_xor_sync(0xffffffff, ps, 2);
            float sc = __expf(fminf(fmaxf(ps * 0.25f, -5.f), 5.f));
            acc.x += sc * vc.x; acc.y += sc * vc.y;
            acc.z += sc * vc.z; acc.w += sc * vc.w;
            accz += sc;
        }
    }

    *(float4*)&g_wV[(long)n * D + lane * 4] = acc;
    if ((lane & 3) == 0) g_z[(long)n * H + (lane >> 2)] = accz;
}

// ---------------- epilogue: attn-norm + Wo + LN1 + FFN + LN2 ---------------
__device__ __forceinline__ void warp_ln4(float* buf, const float* __restrict__ g,
                                         const float* __restrict__ b,
                                         float* outbase, int t)
{
    int w = t >> 5, lane = t & 31;
    float4 gv = *(const float4*)&g[lane * 4];
    float4 bv = *(const float4*)&b[lane * 4];
#pragma unroll
    for (int i = 0; i < 4; i++) {
        int n = w * 4 + i;
        float4 v = *(float4*)&buf[n * D + lane * 4];
        float s  = v.x + v.y + v.z + v.w;
        float sq = v.x * v.x + v.y * v.y + v.z * v.z + v.w * v.w;
#pragma unroll
        for (int off = 16; off >= 1; off >>= 1) {
            s  += __shfl_xor_sync(0xffffffff, s, off);
            sq += __shfl_xor_sync(0xffffffff, sq, off);
        }
        float mu  = s * (1.f / D);
        float var = sq * (1.f / D) - mu * mu;
        float rs  = rsqrtf(var + 1e-5f);
        float4 o;
        o.x = (v.x - mu) * rs * gv.x + bv.x;
        o.y = (v.y - mu) * rs * gv.y + bv.y;
        o.z = (v.z - mu) * rs * gv.z + bv.z;
        o.w = (v.w - mu) * rs * gv.w + bv.w;
        *(float4*)&outbase[n * D + lane * 4] = o;
    }
}

__global__ __launch_bounds__(256) void epi_kernel(
    const float* __restrict__ h,
    const float* __restrict__ Wo, const float* __restrict__ bo,
    const float* __restrict__ ln1g, const float* __restrict__ ln1b,
    const float* __restrict__ W1, const float* __restrict__ b1,
    const float* __restrict__ W2, const float* __restrict__ b2,
    const float* __restrict__ ln2g, const float* __restrict__ ln2b,
    float* __restrict__ out)
{
    __shared__ float sm[12288];           // 48KB
    float* XS = sm;                       // [32][128]
    float* A  = sm + 4096;                // [32][128] h_attn; later reused as FS
    float* FS = sm + 4096;                // [32][256] (A is dead by then)

    int t = threadIdx.x;
    int n0 = blockIdx.x * 32;

    // step 1: h_attn = wV / (z + eps)
    {
        int nl = t >> 3;
        int head = t & 7;
        int gn = n0 + nl;
        float inv = 1.f / (g_z[(long)gn * H + head] + 1e-6f);
        const float4* s4 = (const float4*)&g_wV[(long)gn * D + head * 16];
        float4* a4 = (float4*)&A[nl * D + head * 16];
#pragma unroll
        for (int j = 0; j < 4; j++) {
            float4 v = s4[j];
            v.x *= inv; v.y *= inv; v.z *= inv; v.w *= inv;
            a4[j] = v;
        }
    }
    __syncthreads();

    int col = (t & 31) * 4;
    int nb4 = (t >> 5) * 4;

    // step 2: XS = h + A @ Wo + bo
    {
        u64 acc[4][2];
#pragma unroll
        for (int i = 0; i < 4; i++) { acc[i][0] = 0ull; acc[i][1] = 0ull; }
#pragma unroll 4
        for (int k = 0; k < D; k += 2) {
            ulonglong2 w0 = *(const ulonglong2*)&Wo[k * D + col];
            ulonglong2 w1 = *(const ulonglong2*)&Wo[(k + 1) * D + col];
#pragma unroll
            for (int i = 0; i < 4; i++) {
                float2 ak = *(const float2*)&A[(nb4 + i) * D + k];
                u64 d0 = dup2(ak.x), d1 = dup2(ak.y);
                acc[i][0] = ffma2(d0, w0.x, acc[i][0]);
                acc[i][1] = ffma2(d0, w0.y, acc[i][1]);
                acc[i][0] = ffma2(d1, w1.x, acc[i][0]);
                acc[i][1] = ffma2(d1, w1.y, acc[i][1]);
            }
        }
        float4 bov = *(const float4*)&bo[col];
        __syncthreads();
#pragma unroll
        for (int i = 0; i < 4; i++) {
            float4 hv = *(const float4*)&h[(long)(n0 + nb4 + i) * D + col];
            V4 v; v.p[0] = acc[i][0]; v.p[1] = acc[i][1];
            float4 x;
            x.x = hv.x + v.f.x + bov.x;
            x.y = hv.y + v.f.y + bov.y;
            x.z = hv.z + v.f.z + bov.z;
            x.w = hv.w + v.f.w + bov.w;
            *(float4*)&XS[(nb4 + i) * D + col] = x;
        }
    }
    __syncthreads();

    // step 3: LN1 in place on XS
    warp_ln4(XS, ln1g, ln1b, XS, t);
    __syncthreads();

    // step 4: FS = relu(XS @ W1 + b1)
    {
        int c1  = (t & 63) * 4;
        int nb8 = (t >> 6) * 8;
        u64 acc[8][2];
#pragma unroll
        for (int i = 0; i < 8; i++) { acc[i][0] = 0ull; acc[i][1] = 0ull; }
#pragma unroll 2
        for (int k = 0; k < D; k += 2) {
            ulonglong2 w0 = *(const ulonglong2*)&W1[k * DFF + c1];
            ulonglong2 w1 = *(const ulonglong2*)&W1[(k + 1) * DFF + c1];
#pragma unroll
            for (int i = 0; i < 8; i++) {
                float2 xk = *(const float2*)&XS[(nb8 + i) * D + k];
                u64 d0 = dup2(xk.x), d1 = dup2(xk.y);
                acc[i][0] = ffma2(d0, w0.x, acc[i][0]);
                acc[i][1] = ffma2(d0, w0.y, acc[i][1]);
                acc[i][0] = ffma2(d1, w1.x, acc[i][0]);
                acc[i][1] = ffma2(d1, w1.y, acc[i][1]);
            }
        }
        float4 b1v = *(const float4*)&b1[c1];
        __syncthreads();
#pragma unroll
        for (int i = 0; i < 8; i++) {
            V4 v; v.p[0] = acc[i][0]; v.p[1] = acc[i][1];
            float4 f;
            f.x = fmaxf(v.f.x + b1v.x, 0.f);
            f.y = fmaxf(v.f.y + b1v.y, 0.f);
            f.z = fmaxf(v.f.z + b1v.z, 0.f);
            f.w = fmaxf(v.f.w + b1v.w, 0.f);
            *(float4*)&FS[(nb8 + i) * DFF + c1] = f;
        }
    }
    __syncthreads();

    // step 5: pre-LN2 = XS + FS @ W2 + b2
    {
        u64 acc[4][2];
#pragma unroll
        for (int i = 0; i < 4; i++) { acc[i][0] = 0ull; acc[i][1] = 0ull; }
#pragma unroll 2
        for (int k = 0; k < DFF; k += 2) {
            ulonglong2 w0 = *(const ulonglong2*)&W2[k * D + col];
            ulonglong2 w1 = *(const ulonglong2*)&W2[(k + 1) * D + col];
#pragma unroll
            for (int i = 0; i < 4; i++) {
                float2 fk = *(const float2*)&FS[(nb4 + i) * DFF + k];
                u64 d0 = dup2(fk.x), d1 = dup2(fk.y);
                acc[i][0] = ffma2(d0, w0.x, acc[i][0]);
                acc[i][1] = ffma2(d0, w0.y, acc[i][1]);
                acc[i][0] = ffma2(d1, w1.x, acc[i][0]);
                acc[i][1] = ffma2(d1, w1.y, acc[i][1]);
            }
        }
        __syncthreads();
        float4 b2v = *(const float4*)&b2[col];
#pragma unroll
        for (int i = 0; i < 4; i++) {
            float4 x = *(float4*)&XS[(nb4 + i) * D + col];
            V4 v; v.p[0] = acc[i][0]; v.p[1] = acc[i][1];
            x.x += v.f.x + b2v.x;
            x.y += v.f.y + b2v.y;
            x.z += v.f.z + b2v.z;
            x.w += v.f.w + b2v.w;
            *(float4*)&XS[(nb4 + i) * D + col] = x;
        }
    }
    __syncthreads();

    // step 6: LN2 -> global out
    warp_ln4(XS, ln2g, ln2b, out + (long)n0 * D, t);
}

// ---------------- launch ----------------------------------------------------
extern "C" void kernel_launch(void* const* d_in, const int* in_sizes, int n_in,
                              void* d_out, int out_size)
{
    const float* h    = (const float*)d_in[0];
    const int*   src  = (const int*)  d_in[1];
    const int*   dst  = (const int*)  d_in[2];
    const float* Wq   = (const float*)d_in[3];
    const float* Wk   = (const float*)d_in[4];
    const float* Wv   = (const float*)d_in[5];
    const float* Wo   = (const float*)d_in[6];
    const float* bo   = (const float*)d_in[7];
    const float* ln1g = (const float*)d_in[8];
    const float* ln1b = (const float*)d_in[9];
    const float* W1   = (const float*)d_in[10];
    const float* b1   = (const float*)d_in[11];
    const float* W2   = (const float*)d_in[12];
    const float* b2   = (const float*)d_in[13];
    const float* ln2g = (const float*)d_in[14];
    const float* ln2b = (const float*)d_in[15];
    float* out = (float*)d_out;

    zero_cnt_kernel<<<(N_NODES + 255) / 256, 256>>>();
    scatter_kernel<<<N_EDGES / 256, 256>>>(src, dst);
    dim3 qgrid((N_NODES + 63) / 64, 3);
    qkv_kernel<<<qgrid, 256>>>(h, Wq, Wk, Wv);
    agg_kernel<<<N_NODES / 8, 256>>>();
    epi_kernel<<<N_NODES / 32, 256>>>(h, Wo, bo, ln1g, ln1b,
                                      W1, b1, W2, b2, ln2g, ln2b, out);
}